// round 12
// baseline (speedup 1.0000x reference)
#include <cuda_runtime.h>

// Batched DLT: 262144 independent 8x8 systems, h = pinv(A)@b == solve(A,b).
// R11: ILP-2 done right. R10 let ptxas serialize two sequential solve calls
// (regs stayed 63, spills, 17us). Here the latency-dominated FRONT of the
// computation is written in float2/int2/paired-int64 form — lane .x = system
// j0, lane .y = system j1 — so every stage emits adjacent independent
// instruction pairs the compiler cannot reorder into serial phases. The tail
// (pivot + 3x3 adjugate solve, internally ILP-rich) runs per system.
// Per-system math identical to R9: exact int skeleton, exact 2-instr trunc
// ((int)__fmul_rz), Kahan-compensated hi/lo determinants, fp32 tails.

struct hl2 { float2 h, l; };
struct ll2 { long long x, y; };

static __device__ __forceinline__ float2 mk(float a, float b) { return make_float2(a, b); }
static __device__ __forceinline__ float2 add2(float2 a, float2 b) { return mk(a.x + b.x, a.y + b.y); }
static __device__ __forceinline__ float2 sub2(float2 a, float2 b) { return mk(a.x - b.x, a.y - b.y); }
static __device__ __forceinline__ float2 mul2(float2 a, float2 b) { return mk(a.x * b.x, a.y * b.y); }
static __device__ __forceinline__ float2 fma2(float2 a, float2 b, float2 c) {
    return mk(fmaf(a.x, b.x, c.x), fmaf(a.y, b.y, c.y));
}
static __device__ __forceinline__ float2 rcp2(float2 a) { return mk(__frcp_rn(a.x), __frcp_rn(a.y)); }
// exact trunc(a*b): RZ multiply cannot cross the integer at or below |a*b|.
static __device__ __forceinline__ int2 trz2(float2 a, float2 b) {
    return make_int2((int)__fmul_rz(a.x, b.x), (int)__fmul_rz(a.y, b.y));
}
static __device__ __forceinline__ int2 f2i2(float2 a) { return make_int2((int)a.x, (int)a.y); }
static __device__ __forceinline__ float2 i2f2(int2 a) { return mk((float)a.x, (float)a.y); }
static __device__ __forceinline__ int2 iadd2(int2 a, int2 b) { return make_int2(a.x + b.x, a.y + b.y); }
static __device__ __forceinline__ int2 isub2(int2 a, int2 b) { return make_int2(a.x - b.x, a.y - b.y); }
// a*b - c*d per lane (exact int32)
static __device__ __forceinline__ int2 idet(int2 a, int2 b, int2 c, int2 d) {
    return make_int2(a.x * b.x - c.x * d.x, a.y * b.y - c.y * d.y);
}
// paired int64 dot:  w0*c0 + w1*c1 + w2*c2 + w3*c3  per lane (exact, < 2^43)
static __device__ __forceinline__ ll2 dot4(int2 w0, int2 w1, int2 w2, int2 w3,
                                           int2 c0, int2 c1, int2 c2, int2 c3) {
    ll2 r;
    r.x = (long long)w0.x * c0.x + (long long)w1.x * c1.x
        + (long long)w2.x * c2.x + (long long)w3.x * c3.x;
    r.y = (long long)w0.y * c0.y + (long long)w1.y * c1.y
        + (long long)w2.y * c2.y + (long long)w3.y * c3.y;
    return r;
}
static __device__ __forceinline__ hl2 split2(ll2 v) {   // exact for |v|<2^48
    float hx = (float)v.x, hy = (float)v.y;
    float lx = (float)(v.x - (long long)hx);
    float ly = (float)(v.y - (long long)hy);
    hl2 r; r.h = mk(hx, hy); r.l = mk(lx, ly); return r;
}
// Kahan a*b - c*e per lane (~1.5 ulp)
static __device__ __forceinline__ float2 kdet2(float2 a, float2 b, float2 c, float2 e) {
    float wx = c.x * e.x,              wy = c.y * e.y;
    float e1x = fmaf(c.x, e.x, -wx),   e1y = fmaf(c.y, e.y, -wy);
    float fx = fmaf(a.x, b.x, -wx),    fy = fmaf(a.y, b.y, -wy);
    return mk(fx - e1x, fy - e1y);
}

// Per-system tail: pivot + shared 3x3 adjugate solve + store. Internally
// ILP-rich (6 independent dot products), so two sequential calls still overlap.
static __device__ __forceinline__ void tail_one(
    int tu0, int tv0, int tu1, int tv1, int tu2, int tv2, int tu3, int tv3,
    int w0, int w1, int w2, int w3,
    float gx0, float gx1, float gx2, float gx3,
    float gy0, float gy1, float gy2, float gy3,
    float z1, float z2, float* __restrict__ o)
{
    int aw0 = abs(w0), aw1 = abs(w1), aw2 = abs(w2), aw3 = abs(w3);
    int k = 0, awm = aw0;
    if (aw1 > awm) { k = 1; awm = aw1; }
    if (aw2 > awm) { k = 2; awm = aw2; }
    if (aw3 > awm) { k = 3; awm = aw3; }
    bool c0 = (k == 0), c1 = (k <= 1), c2 = (k <= 2);

    int A1i = c0 ? tu1 : tu0,  B1i = c0 ? tv1 : tv0;
    int A2i = c1 ? tu2 : tu1,  B2i = c1 ? tv2 : tv1;
    int A3i = c2 ? tu3 : tu2,  B3i = c2 ? tv3 : tv2;
    float G1x = c0 ? gx1 : gx0, G1y = c0 ? gy1 : gy0;
    float G2x = c1 ? gx2 : gx1, G2y = c1 ? gy2 : gy1;
    float G3x = c2 ? gx3 : gx2, G3y = c2 ? gy3 : gy2;

    int E12 = A1i * B2i - A2i * B1i;
    int E23 = A2i * B3i - A3i * B2i;
    int E31 = A3i * B1i - A1i * B3i;
    int det3 = E12 + E23 + E31;
    float inv3 = __frcp_rn((float)det3);

    float r11 = (float)(B2i - B3i), r12 = (float)(B3i - B1i), r13 = (float)(B1i - B2i);
    float r21 = (float)(A3i - A2i), r22 = (float)(A1i - A3i), r23 = (float)(A2i - A1i);
    float e12 = (float)E12, e23 = (float)E23, e31 = (float)E31;

    o[0] = fmaf(r11, G1x, fmaf(r12, G2x, r13 * G3x)) * inv3;
    o[1] = fmaf(r21, G1x, fmaf(r22, G2x, r23 * G3x)) * inv3;
    o[2] = fmaf(e23, G1x, fmaf(e31, G2x, e12 * G3x)) * inv3;
    o[3] = fmaf(r11, G1y, fmaf(r12, G2y, r13 * G3y)) * inv3;
    o[4] = fmaf(r21, G1y, fmaf(r22, G2y, r23 * G3y)) * inv3;
    o[5] = fmaf(e23, G1y, fmaf(e31, G2y, e12 * G3y)) * inv3;
    o[6] = z1;
    o[7] = z2;
    o[8] = 1.0f;
}

__global__ __launch_bounds__(128)
void dlt_kernel(const float* __restrict__ x, const float* __restrict__ xp,
                float* __restrict__ out, int B, int T)
{
    int t = blockIdx.x * blockDim.x + threadIdx.x;
    if (t >= T) return;
    int j0 = t;
    int j1 = t + T;
    if (j1 >= B) j1 = j0;        // odd-B guard: redundant but deterministic

    const float4* xv  = reinterpret_cast<const float4*>(x);
    const float4* xpv = reinterpret_cast<const float4*>(xp);

    float4 a0A = xv[2*j0],  a1A = xv[2*j0 + 1];
    float4 a0B = xv[2*j1],  a1B = xv[2*j1 + 1];
    float4 p0A = xpv[2*j0], p1A = xpv[2*j0 + 1];
    float4 p0B = xpv[2*j1], p1B = xpv[2*j1 + 1];

    // Lane .x = system j0, lane .y = system j1.
    float2 u0 = mk(a0A.x, a0B.x), v0 = mk(a0A.y, a0B.y);
    float2 u1 = mk(a0A.z, a0B.z), v1 = mk(a0A.w, a0B.w);
    float2 u2 = mk(a1A.x, a1B.x), v2 = mk(a1A.y, a1B.y);
    float2 u3 = mk(a1A.z, a1B.z), v3 = mk(a1A.w, a1B.w);
    float2 up0 = mk(p0A.x, p0B.x), vp0 = mk(p0A.y, p0B.y);
    float2 up1 = mk(p0A.z, p0B.z), vp1 = mk(p0A.w, p0B.w);
    float2 up2 = mk(p1A.x, p1B.x), vp2 = mk(p1A.y, p1B.y);
    float2 up3 = mk(p1A.z, p1B.z), vp3 = mk(p1A.w, p1B.w);

    // trunc of raw coordinates: exact F2I.
    int2 tu0 = f2i2(u0), tv0 = f2i2(v0), tu1 = f2i2(u1), tv1 = f2i2(v1);
    int2 tu2 = f2i2(u2), tv2 = f2i2(v2), tu3 = f2i2(u3), tv3 = f2i2(v3);

    // trunc(vp*u) etc. — exact via RZ multiply + F2I.
    int2 cu0 = trz2(vp0, u0), cu1 = trz2(vp1, u1), cu2 = trz2(vp2, u2), cu3 = trz2(vp3, u3);
    int2 cv0 = trz2(vp0, v0), cv1 = trz2(vp1, v1), cv2 = trz2(vp2, v2), cv3 = trz2(vp3, v3);
    int2 du0 = trz2(up0, u0), du1 = trz2(up1, u1), du2 = trz2(up2, u2), du3 = trz2(up3, u3);
    int2 dv0 = trz2(up0, v0), dv1 = trz2(up1, v1), dv2 = trz2(up2, v2), dv3 = trz2(up3, v3);

    // Pairwise dets + left null vector w — exact int32, paired lanes.
    int2 D01 = idet(tu0, tv1, tu1, tv0);
    int2 D02 = idet(tu0, tv2, tu2, tv0);
    int2 D03 = idet(tu0, tv3, tu3, tv0);
    int2 D12 = idet(tu1, tv2, tu2, tv1);
    int2 D13 = idet(tu1, tv3, tu3, tv1);
    int2 D23 = idet(tu2, tv3, tu3, tv2);
    int2 w0 = isub2(iadd2(D12, D23), D13);
    int2 w1 = isub2(isub2(D03, D02), D23);
    int2 w2 = isub2(iadd2(D01, D13), D03);
    int2 w3 = isub2(isub2(D02, D01), D12);

    // 2x2 normal-matrix entries — exact int64 per lane, hi/lo split.
    hl2 A11 = split2(dot4(w0, w1, w2, w3, cu0, cu1, cu2, cu3));
    hl2 A12 = split2(dot4(w0, w1, w2, w3, cv0, cv1, cv2, cv3));
    hl2 A21 = split2(dot4(w0, w1, w2, w3, du0, du1, du2, du3));
    hl2 A22 = split2(dot4(w0, w1, w2, w3, dv0, dv1, dv2, dv3));

    // b-dots in plain fp32 (paired).
    float2 w0f = i2f2(w0), w1f = i2f2(w1), w2f = i2f2(w2), w3f = i2f2(w3);
    float2 zero = mk(0.0f, 0.0f);
    float2 b1 = sub2(zero, fma2(w0f, vp0, fma2(w1f, vp1, fma2(w2f, vp2, mul2(w3f, vp3)))));
    float2 b2 = sub2(zero, fma2(w0f, up0, fma2(w1f, up1, fma2(w2f, up2, mul2(w3f, up3)))));

    // det2 = A11*A22 - A12*A21: Kahan hi diff + hi*lo cross corrections.
    float2 d0 = kdet2(A11.h, A22.h, A12.h, A21.h);
    float2 dc = fma2(A11.h, A22.l,
               fma2(A11.l, A22.h,
               sub2(zero, fma2(A12.h, A21.l, mul2(A12.l, A21.h)))));
    float2 det2 = add2(d0, dc);

    // Cramer numerators.
    float2 n1 = add2(kdet2(A22.h, b1, A12.h, b2),
                     fma2(A22.l, b1, sub2(zero, mul2(A12.l, b2))));
    float2 n2 = add2(kdet2(A11.h, b2, A21.h, b1),
                     fma2(A11.l, b2, sub2(zero, mul2(A21.l, b1))));

    float2 inv2 = rcp2(det2);
    float2 z1 = mul2(n1, inv2);
    float2 z2 = mul2(n2, inv2);

    // RHS of the two 3x3 solves — plain fp32, paired.
    float2 gx0 = fma2(i2f2(du0), z1, fma2(i2f2(dv0), z2, up0));
    float2 gx1 = fma2(i2f2(du1), z1, fma2(i2f2(dv1), z2, up1));
    float2 gx2 = fma2(i2f2(du2), z1, fma2(i2f2(dv2), z2, up2));
    float2 gx3 = fma2(i2f2(du3), z1, fma2(i2f2(dv3), z2, up3));
    float2 gy0 = fma2(i2f2(cu0), z1, fma2(i2f2(cv0), z2, vp0));
    float2 gy1 = fma2(i2f2(cu1), z1, fma2(i2f2(cv1), z2, vp1));
    float2 gy2 = fma2(i2f2(cu2), z1, fma2(i2f2(cv2), z2, vp2));
    float2 gy3 = fma2(i2f2(cu3), z1, fma2(i2f2(cv3), z2, vp3));

    // Per-system tails (each internally ILP-rich).
    tail_one(tu0.x, tv0.x, tu1.x, tv1.x, tu2.x, tv2.x, tu3.x, tv3.x,
             w0.x, w1.x, w2.x, w3.x,
             gx0.x, gx1.x, gx2.x, gx3.x, gy0.x, gy1.x, gy2.x, gy3.x,
             z1.x, z2.x, out + (size_t)j0 * 9);
    tail_one(tu0.y, tv0.y, tu1.y, tv1.y, tu2.y, tv2.y, tu3.y, tv3.y,
             w0.y, w1.y, w2.y, w3.y,
             gx0.y, gx1.y, gx2.y, gx3.y, gy0.y, gy1.y, gy2.y, gy3.y,
             z1.y, z2.y, out + (size_t)j1 * 9);
}

extern "C" void kernel_launch(void* const* d_in, const int* in_sizes, int n_in,
                              void* d_out, int out_size)
{
    const float* x  = (const float*)d_in[0];
    const float* xp = (const float*)d_in[1];
    float* out = (float*)d_out;
    int B = in_sizes[0] / 8;
    int Bo = out_size / 9;
    if (Bo < B) B = Bo;
    int T = (B + 1) / 2;                 // threads; lane pair = (t, t+T)
    dlt_kernel<<<(T + 127) / 128, 128>>>(x, xp, out, B, T);
}

// round 13
// speedup vs baseline: 1.3744x; 1.3744x over previous
#include <cuda_runtime.h>

// Batched DLT: 262144 independent 8x8 systems, h = pinv(A)@b == solve(A,b).
// R13 = R9 math (best: 12.8us) + three scheduling fixes, no math changes:
//  1. persistent single wave: T=B/2 threads, each solves systems (t, t+T)
//     sequentially -> 1024 CTAs = exactly one wave at 7 CTAs/SM.
//  2. prefetch: system-2 loads issued before system-1 compute (DRAM latency
//     hidden under the ~1500-cycle compute chain).
//  3. coalesced stores: 9 floats staged in smem (stride-9 write pattern is
//     bank-conflict-free, gcd(9,32)=1), then 9 coalesced STG.32 per warp
//     (9 L1 wavefronts instead of 81).
// Math per system identical to R9: exact int skeleton, exact 2-instr trunc
// ((int)__fmul_rz), Kahan-compensated hi/lo determinants, fp32 tails.

struct hl { float h, l; };

__device__ __forceinline__ hl split_ll(long long v) {   // exact for |v|<2^48
    float h = (float)v;
    float l = (float)(v - (long long)h);
    return hl{h, l};
}

// Kahan: a*b - c*e with ~1.5 ulp error (flat 4-op tree).
__device__ __forceinline__ float kdet(float a, float b, float c, float e) {
    float w  = c * e;
    float e1 = fmaf(c, e, -w);
    float f  = fmaf(a, b, -w);
    return f - e1;
}

// Solves one system; writes h[0..8] to o (stride 1, smem).
__device__ __forceinline__ void solve_one(float4 a0, float4 a1,
                                          float4 p0, float4 p1,
                                          float* __restrict__ o)
{
    float u0 = a0.x, v0 = a0.y, u1 = a0.z, v1 = a0.w;
    float u2 = a1.x, v2 = a1.y, u3 = a1.z, v3 = a1.w;
    float up0 = p0.x, vp0 = p0.y, up1 = p0.z, vp1 = p0.w;
    float up2 = p1.x, vp2 = p1.y, up3 = p1.z, vp3 = p1.w;

    int tu0 = (int)u0, tv0 = (int)v0, tu1 = (int)u1, tv1 = (int)v1;
    int tu2 = (int)u2, tv2 = (int)v2, tu3 = (int)u3, tv3 = (int)v3;

    // exact trunc(a*b): RZ multiply cannot cross the integer at/below |a*b|.
    int cu0 = (int)__fmul_rz(vp0, u0), cu1 = (int)__fmul_rz(vp1, u1);
    int cu2 = (int)__fmul_rz(vp2, u2), cu3 = (int)__fmul_rz(vp3, u3);
    int cv0 = (int)__fmul_rz(vp0, v0), cv1 = (int)__fmul_rz(vp1, v1);
    int cv2 = (int)__fmul_rz(vp2, v2), cv3 = (int)__fmul_rz(vp3, v3);
    int du0 = (int)__fmul_rz(up0, u0), du1 = (int)__fmul_rz(up1, u1);
    int du2 = (int)__fmul_rz(up2, u2), du3 = (int)__fmul_rz(up3, u3);
    int dv0 = (int)__fmul_rz(up0, v0), dv1 = (int)__fmul_rz(up1, v1);
    int dv2 = (int)__fmul_rz(up2, v2), dv3 = (int)__fmul_rz(up3, v3);

    int D01 = tu0*tv1 - tu1*tv0;
    int D02 = tu0*tv2 - tu2*tv0;
    int D03 = tu0*tv3 - tu3*tv0;
    int D12 = tu1*tv2 - tu2*tv1;
    int D13 = tu1*tv3 - tu3*tv1;
    int D23 = tu2*tv3 - tu3*tv2;
    int w0 = D12 + D23 - D13;
    int w1 = D03 - D02 - D23;
    int w2 = D01 + D13 - D03;
    int w3 = D02 - D01 - D12;

    long long a11 = (long long)w0*cu0 + (long long)w1*cu1 + (long long)w2*cu2 + (long long)w3*cu3;
    long long a12 = (long long)w0*cv0 + (long long)w1*cv1 + (long long)w2*cv2 + (long long)w3*cv3;
    long long a21 = (long long)w0*du0 + (long long)w1*du1 + (long long)w2*du2 + (long long)w3*du3;
    long long a22 = (long long)w0*dv0 + (long long)w1*dv1 + (long long)w2*dv2 + (long long)w3*dv3;
    hl A11 = split_ll(a11), A12 = split_ll(a12);
    hl A21 = split_ll(a21), A22 = split_ll(a22);

    float w0f = (float)w0, w1f = (float)w1, w2f = (float)w2, w3f = (float)w3;
    float b1 = -fmaf(w0f, vp0, fmaf(w1f, vp1, fmaf(w2f, vp2, w3f * vp3)));
    float b2 = -fmaf(w0f, up0, fmaf(w1f, up1, fmaf(w2f, up2, w3f * up3)));

    float d0 = kdet(A11.h, A22.h, A12.h, A21.h);
    float dc = fmaf(A11.h, A22.l,
               fmaf(A11.l, A22.h,
              -fmaf(A12.h, A21.l, A12.l * A21.h)));
    float det2 = d0 + dc;

    float n1 = kdet(A22.h, b1, A12.h, b2) + fmaf(A22.l, b1, -(A12.l * b2));
    float n2 = kdet(A11.h, b2, A21.h, b1) + fmaf(A11.l, b2, -(A21.l * b1));

    float inv2 = __frcp_rn(det2);
    float z1 = n1 * inv2;
    float z2 = n2 * inv2;

    float gx0 = fmaf((float)du0, z1, fmaf((float)dv0, z2, up0));
    float gx1 = fmaf((float)du1, z1, fmaf((float)dv1, z2, up1));
    float gx2 = fmaf((float)du2, z1, fmaf((float)dv2, z2, up2));
    float gx3 = fmaf((float)du3, z1, fmaf((float)dv3, z2, up3));
    float gy0 = fmaf((float)cu0, z1, fmaf((float)cv0, z2, vp0));
    float gy1 = fmaf((float)cu1, z1, fmaf((float)cv1, z2, vp1));
    float gy2 = fmaf((float)cu2, z1, fmaf((float)cv2, z2, vp2));
    float gy3 = fmaf((float)cu3, z1, fmaf((float)cv3, z2, vp3));

    int aw0 = abs(w0), aw1 = abs(w1), aw2 = abs(w2), aw3 = abs(w3);
    int k = 0, awm = aw0;
    if (aw1 > awm) { k = 1; awm = aw1; }
    if (aw2 > awm) { k = 2; awm = aw2; }
    if (aw3 > awm) { k = 3; awm = aw3; }
    bool c0 = (k == 0), c1 = (k <= 1), c2 = (k <= 2);

    int A1i = c0 ? tu1 : tu0,  B1i = c0 ? tv1 : tv0;
    int A2i = c1 ? tu2 : tu1,  B2i = c1 ? tv2 : tv1;
    int A3i = c2 ? tu3 : tu2,  B3i = c2 ? tv3 : tv2;
    float G1x = c0 ? gx1 : gx0, G1y = c0 ? gy1 : gy0;
    float G2x = c1 ? gx2 : gx1, G2y = c1 ? gy2 : gy1;
    float G3x = c2 ? gx3 : gx2, G3y = c2 ? gy3 : gy2;

    int E12 = A1i*B2i - A2i*B1i;
    int E23 = A2i*B3i - A3i*B2i;
    int E31 = A3i*B1i - A1i*B3i;
    int det3 = E12 + E23 + E31;
    float inv3 = __frcp_rn((float)det3);

    float r11 = (float)(B2i - B3i), r12 = (float)(B3i - B1i), r13 = (float)(B1i - B2i);
    float r21 = (float)(A3i - A2i), r22 = (float)(A1i - A3i), r23 = (float)(A2i - A1i);
    float e12 = (float)E12, e23 = (float)E23, e31 = (float)E31;

    o[0] = fmaf(r11, G1x, fmaf(r12, G2x, r13 * G3x)) * inv3;
    o[1] = fmaf(r21, G1x, fmaf(r22, G2x, r23 * G3x)) * inv3;
    o[2] = fmaf(e23, G1x, fmaf(e31, G2x, e12 * G3x)) * inv3;
    o[3] = fmaf(r11, G1y, fmaf(r12, G2y, r13 * G3y)) * inv3;
    o[4] = fmaf(r21, G1y, fmaf(r22, G2y, r23 * G3y)) * inv3;
    o[5] = fmaf(e23, G1y, fmaf(e31, G2y, e12 * G3y)) * inv3;
    o[6] = z1;
    o[7] = z2;
    o[8] = 1.0f;
}

__global__ __launch_bounds__(128, 7)
void dlt_kernel(const float* __restrict__ x, const float* __restrict__ xp,
                float* __restrict__ out, int B, int T)
{
    __shared__ float stage[4][288];     // per-warp 32 systems x 9 floats
    int t = blockIdx.x * blockDim.x + threadIdx.x;
    int lane = threadIdx.x & 31;
    int warp = threadIdx.x >> 5;
    float* srow = stage[warp];

    int j0 = t < T ? t : (T - 1);       // clamp; guarded at store
    int j1 = j0 + T;
    bool has2 = (j1 < B);

    const float4* xv  = reinterpret_cast<const float4*>(x);
    const float4* xpv = reinterpret_cast<const float4*>(xp);

    // System-1 loads.
    float4 a0 = xv[2*j0], a1 = xv[2*j0 + 1];
    float4 p0 = xpv[2*j0], p1 = xpv[2*j0 + 1];
    // System-2 prefetch — issued before system-1 compute; latency hides
    // under the ~1500-cycle solve chain.
    int j1c = has2 ? j1 : j0;
    float4 b0 = xv[2*j1c], b1v = xv[2*j1c + 1];
    float4 q0 = xpv[2*j1c], q1 = xpv[2*j1c + 1];

    // ---- system 1 ----
    solve_one(a0, a1, p0, p1, srow + lane * 9);
    __syncwarp();
    {
        // warp's 32 systems start at (t & ~31); coalesced 288-float tile.
        size_t base = (size_t)(t & ~31) * 9;
        size_t lim  = (size_t)T * 9;    // pass-1 owns systems < T
        #pragma unroll
        for (int c = 0; c < 9; c++) {
            size_t idx = base + lane + 32 * c;
            if (idx < lim) out[idx] = srow[lane + 32 * c];
        }
    }
    __syncwarp();

    // ---- system 2 ----
    solve_one(b0, b1v, q0, q1, srow + lane * 9);
    __syncwarp();
    {
        size_t base = ((size_t)(t & ~31) + T) * 9;
        size_t lim  = (size_t)B * 9;    // pass-2 owns systems in [T, B)
        #pragma unroll
        for (int c = 0; c < 9; c++) {
            size_t idx = base + lane + 32 * c;
            if (idx < lim) out[idx] = srow[lane + 32 * c];
        }
    }
}

extern "C" void kernel_launch(void* const* d_in, const int* in_sizes, int n_in,
                              void* d_out, int out_size)
{
    const float* x  = (const float*)d_in[0];
    const float* xp = (const float*)d_in[1];
    float* out = (float*)d_out;
    int B = in_sizes[0] / 8;
    int Bo = out_size / 9;
    if (Bo < B) B = Bo;
    int T = (B + 1) / 2;                       // thread count; pair (t, t+T)
    dlt_kernel<<<(T + 127) / 128, 128>>>(x, xp, out, B, T);
}

// round 14
// speedup vs baseline: 1.3922x; 1.0130x over previous
#include <cuda_runtime.h>

// Batched DLT: 262144 independent 8x8 systems, h = pinv(A)@b == solve(A,b).
// R14 = R13 (12.48us: single wave, prefetch, smem-staged stores) + two diets:
//  1. fp32 trunc-skeleton: tu/tv < 2^11 so all pairwise dets/cofactors are
//     EXACT in fp32 (integer results < 2^24; fmaf of exact products rounds
//     once to an integer < 2^24 => exact). Kills ~25 F2I/I2F converts per
//     system (20-cyc, half-rate pipe) and moves D/E/r/det3 from the 13%-busy
//     alu pipe to fma. w still feeds the exact int64 dot via 4 F2I.
//  2. float4 flush of the staged 288-float warp tile (16B-aligned):
//     3 LDS.128+STG.128 rounds instead of 9 scalar pairs per system.
// Core precision chain unchanged: exact RZ-trunc, exact int64 normal-matrix
// dots, Kahan-compensated hi/lo determinants, fp32 tails.

struct hl { float h, l; };

__device__ __forceinline__ hl split_ll(long long v) {   // exact for |v|<2^48
    float h = (float)v;
    float l = (float)(v - (long long)h);
    return hl{h, l};
}

// Kahan: a*b - c*e with ~1.5 ulp error (flat 4-op tree).
__device__ __forceinline__ float kdet(float a, float b, float c, float e) {
    float w  = c * e;
    float e1 = fmaf(c, e, -w);
    float f  = fmaf(a, b, -w);
    return f - e1;
}

// Exact a*b - c*d for integer-valued fp32 inputs with |products| < 2^24.
__device__ __forceinline__ float fdet(float a, float b, float c, float d) {
    return fmaf(a, b, -(c * d));
}

// Solves one system; writes h[0..8] to o (stride 1, smem).
__device__ __forceinline__ void solve_one(float4 a0, float4 a1,
                                          float4 p0, float4 p1,
                                          float* __restrict__ o)
{
    float u0 = a0.x, v0 = a0.y, u1 = a0.z, v1 = a0.w;
    float u2 = a1.x, v2 = a1.y, u3 = a1.z, v3 = a1.w;
    float up0 = p0.x, vp0 = p0.y, up1 = p0.z, vp1 = p0.w;
    float up2 = p1.x, vp2 = p1.y, up3 = p1.z, vp3 = p1.w;

    // trunc of raw coordinates — exact, stays in fp32.
    float tu0 = truncf(u0), tv0 = truncf(v0), tu1 = truncf(u1), tv1 = truncf(v1);
    float tu2 = truncf(u2), tv2 = truncf(v2), tu3 = truncf(u3), tv3 = truncf(v3);

    // exact trunc(a*b): RZ product cannot cross the integer at/below |a*b|.
    // Keep both float (for g-RHS) and int (for exact int64 dots) forms;
    // both convert from the same RZ product, in parallel.
    float rcu0 = __fmul_rz(vp0, u0), rcu1 = __fmul_rz(vp1, u1);
    float rcu2 = __fmul_rz(vp2, u2), rcu3 = __fmul_rz(vp3, u3);
    float rcv0 = __fmul_rz(vp0, v0), rcv1 = __fmul_rz(vp1, v1);
    float rcv2 = __fmul_rz(vp2, v2), rcv3 = __fmul_rz(vp3, v3);
    float rdu0 = __fmul_rz(up0, u0), rdu1 = __fmul_rz(up1, u1);
    float rdu2 = __fmul_rz(up2, u2), rdu3 = __fmul_rz(up3, u3);
    float rdv0 = __fmul_rz(up0, v0), rdv1 = __fmul_rz(up1, v1);
    float rdv2 = __fmul_rz(up2, v2), rdv3 = __fmul_rz(up3, v3);
    int cu0 = (int)rcu0, cu1 = (int)rcu1, cu2 = (int)rcu2, cu3 = (int)rcu3;
    int cv0 = (int)rcv0, cv1 = (int)rcv1, cv2 = (int)rcv2, cv3 = (int)rcv3;
    int du0 = (int)rdu0, du1 = (int)rdu1, du2 = (int)rdu2, du3 = (int)rdu3;
    int dv0 = (int)rdv0, dv1 = (int)rdv1, dv2 = (int)rdv2, dv3 = (int)rdv3;
    float cu0f = truncf(rcu0), cu1f = truncf(rcu1), cu2f = truncf(rcu2), cu3f = truncf(rcu3);
    float cv0f = truncf(rcv0), cv1f = truncf(rcv1), cv2f = truncf(rcv2), cv3f = truncf(rcv3);
    float du0f = truncf(rdu0), du1f = truncf(rdu1), du2f = truncf(rdu2), du3f = truncf(rdu3);
    float dv0f = truncf(rdv0), dv1f = truncf(rdv1), dv2f = truncf(rdv2), dv3f = truncf(rdv3);

    // Pairwise dets + left null vector w — EXACT fp32 (integers < 2^24).
    float D01 = fdet(tu0, tv1, tu1, tv0);
    float D02 = fdet(tu0, tv2, tu2, tv0);
    float D03 = fdet(tu0, tv3, tu3, tv0);
    float D12 = fdet(tu1, tv2, tu2, tv1);
    float D13 = fdet(tu1, tv3, tu3, tv1);
    float D23 = fdet(tu2, tv3, tu3, tv2);
    float w0f = D12 + D23 - D13;
    float w1f = D03 - D02 - D23;
    float w2f = D01 + D13 - D03;
    float w3f = D02 - D01 - D12;
    int w0 = (int)w0f, w1 = (int)w1f, w2 = (int)w2f, w3 = (int)w3f;

    // 2x2 normal-matrix entries — exact int64 (|.| < 2^43), hi/lo split.
    long long a11 = (long long)w0*cu0 + (long long)w1*cu1 + (long long)w2*cu2 + (long long)w3*cu3;
    long long a12 = (long long)w0*cv0 + (long long)w1*cv1 + (long long)w2*cv2 + (long long)w3*cv3;
    long long a21 = (long long)w0*du0 + (long long)w1*du1 + (long long)w2*du2 + (long long)w3*du3;
    long long a22 = (long long)w0*dv0 + (long long)w1*dv1 + (long long)w2*dv2 + (long long)w3*dv3;
    hl A11 = split_ll(a11), A12 = split_ll(a12);
    hl A21 = split_ll(a21), A22 = split_ll(a22);

    // b-dots in plain fp32 (w exact in fp32 already).
    float b1 = -fmaf(w0f, vp0, fmaf(w1f, vp1, fmaf(w2f, vp2, w3f * vp3)));
    float b2 = -fmaf(w0f, up0, fmaf(w1f, up1, fmaf(w2f, up2, w3f * up3)));

    // det2 = A11*A22 - A12*A21: Kahan hi diff + hi*lo cross corrections.
    float d0 = kdet(A11.h, A22.h, A12.h, A21.h);
    float dc = fmaf(A11.h, A22.l,
               fmaf(A11.l, A22.h,
              -fmaf(A12.h, A21.l, A12.l * A21.h)));
    float det2 = d0 + dc;

    float n1 = kdet(A22.h, b1, A12.h, b2) + fmaf(A22.l, b1, -(A12.l * b2));
    float n2 = kdet(A11.h, b2, A21.h, b1) + fmaf(A11.l, b2, -(A21.l * b1));

    float inv2 = __frcp_rn(det2);
    float z1 = n1 * inv2;
    float z2 = n2 * inv2;

    // RHS of the two 3x3 solves — plain fp32 (cu..dv float forms, exact).
    float gx0 = fmaf(du0f, z1, fmaf(dv0f, z2, up0));
    float gx1 = fmaf(du1f, z1, fmaf(dv1f, z2, up1));
    float gx2 = fmaf(du2f, z1, fmaf(dv2f, z2, up2));
    float gx3 = fmaf(du3f, z1, fmaf(dv3f, z2, up3));
    float gy0 = fmaf(cu0f, z1, fmaf(cv0f, z2, vp0));
    float gy1 = fmaf(cu1f, z1, fmaf(cv1f, z2, vp1));
    float gy2 = fmaf(cu2f, z1, fmaf(cv2f, z2, vp2));
    float gy3 = fmaf(cu3f, z1, fmaf(cv3f, z2, vp3));

    // Pivot: drop row argmax|w| (fp32 compares on exact integers).
    float aw0 = fabsf(w0f), aw1 = fabsf(w1f), aw2 = fabsf(w2f), aw3 = fabsf(w3f);
    int k = 0; float awm = aw0;
    if (aw1 > awm) { k = 1; awm = aw1; }
    if (aw2 > awm) { k = 2; awm = aw2; }
    if (aw3 > awm) { k = 3; awm = aw3; }
    bool c0 = (k == 0), c1 = (k <= 1), c2 = (k <= 2);

    float A1 = c0 ? tu1 : tu0,  B1 = c0 ? tv1 : tv0;
    float A2 = c1 ? tu2 : tu1,  B2 = c1 ? tv2 : tv1;
    float A3 = c2 ? tu3 : tu2,  B3 = c2 ? tv3 : tv2;
    float G1x = c0 ? gx1 : gx0, G1y = c0 ? gy1 : gy0;
    float G2x = c1 ? gx2 : gx1, G2y = c1 ? gy2 : gy1;
    float G3x = c2 ? gx3 : gx2, G3y = c2 ? gy3 : gy2;

    // 3x3 adjugate — EXACT fp32 (integer cofactors < 2^23).
    float e12 = fdet(A1, B2, A2, B1);
    float e23 = fdet(A2, B3, A3, B2);
    float e31 = fdet(A3, B1, A1, B3);
    float det3 = e12 + e23 + e31;
    float inv3 = __frcp_rn(det3);

    float r11 = B2 - B3, r12 = B3 - B1, r13 = B1 - B2;
    float r21 = A3 - A2, r22 = A1 - A3, r23 = A2 - A1;

    o[0] = fmaf(r11, G1x, fmaf(r12, G2x, r13 * G3x)) * inv3;
    o[1] = fmaf(r21, G1x, fmaf(r22, G2x, r23 * G3x)) * inv3;
    o[2] = fmaf(e23, G1x, fmaf(e31, G2x, e12 * G3x)) * inv3;
    o[3] = fmaf(r11, G1y, fmaf(r12, G2y, r13 * G3y)) * inv3;
    o[4] = fmaf(r21, G1y, fmaf(r22, G2y, r23 * G3y)) * inv3;
    o[5] = fmaf(e23, G1y, fmaf(e31, G2y, e12 * G3y)) * inv3;
    o[6] = z1;
    o[7] = z2;
    o[8] = 1.0f;
}

// Flush a warp's staged 288-float tile (16B-aligned) to out+base.
__device__ __forceinline__ void flush_tile(float* __restrict__ out,
                                           const float* __restrict__ srow,
                                           size_t base, int lane,
                                           bool full, size_t lim)
{
    if (full) {
        const float4* s4 = reinterpret_cast<const float4*>(srow);
        float4* o4 = reinterpret_cast<float4*>(out + base);
        o4[lane]      = s4[lane];
        o4[lane + 32] = s4[lane + 32];
        if (lane < 8) o4[lane + 64] = s4[lane + 64];
    } else {
        #pragma unroll
        for (int c = 0; c < 9; c++) {
            size_t idx = base + lane + 32 * c;
            if (idx < lim) out[idx] = srow[lane + 32 * c];
        }
    }
}

__global__ __launch_bounds__(128, 7)
void dlt_kernel(const float* __restrict__ x, const float* __restrict__ xp,
                float* __restrict__ out, int B, int T)
{
    __shared__ __align__(16) float stage[4][288];   // per-warp 32x9 floats
    int t = blockIdx.x * blockDim.x + threadIdx.x;
    int lane = threadIdx.x & 31;
    int warp = threadIdx.x >> 5;
    float* srow = stage[warp];

    int j0 = t < T ? t : (T - 1);       // clamp; guarded at store
    int j1 = j0 + T;
    bool has2 = (j1 < B);

    const float4* xv  = reinterpret_cast<const float4*>(x);
    const float4* xpv = reinterpret_cast<const float4*>(xp);

    // System-1 loads + system-2 prefetch (hides DRAM under solve 1).
    float4 a0 = xv[2*j0], a1 = xv[2*j0 + 1];
    float4 p0 = xpv[2*j0], p1 = xpv[2*j0 + 1];
    int j1c = has2 ? j1 : j0;
    float4 b0 = xv[2*j1c], b1v = xv[2*j1c + 1];
    float4 q0 = xpv[2*j1c], q1 = xpv[2*j1c + 1];

    int tb = t & ~31;

    // ---- system 1 ----
    solve_one(a0, a1, p0, p1, srow + lane * 9);
    __syncwarp();
    flush_tile(out, srow, (size_t)tb * 9, lane,
               (tb + 31 < T), (size_t)T * 9);
    __syncwarp();

    // ---- system 2 ----
    solve_one(b0, b1v, q0, q1, srow + lane * 9);
    __syncwarp();
    flush_tile(out, srow, ((size_t)tb + T) * 9, lane,
               (tb + T + 31 < B), (size_t)B * 9);
}

extern "C" void kernel_launch(void* const* d_in, const int* in_sizes, int n_in,
                              void* d_out, int out_size)
{
    const float* x  = (const float*)d_in[0];
    const float* xp = (const float*)d_in[1];
    float* out = (float*)d_out;
    int B = in_sizes[0] / 8;
    int Bo = out_size / 9;
    if (Bo < B) B = Bo;
    int T = (B + 1) / 2;                       // thread count; pair (t, t+T)
    dlt_kernel<<<(T + 127) / 128, 128>>>(x, xp, out, B, T);
}